// round 1
// baseline (speedup 1.0000x reference)
#include <cuda_runtime.h>

// Problem constants
#define BB 4096
#define LL 5
#define DD 128
#define NHH 16
#define NVV 4
#define TT 100
#define FC1 752

#define RB 32          // rows per block
#define NTHR 512       // threads per block
#define NWARP 16

// Shared memory layout (floats)
//  s_emb  [RB][5][128] = 20480   (aliased by s_xc[RB][256] = 8192 after hor)
//  s_z    [RB][752]    = 24064
//  s_wh   max 16*5*128 = 10240   (aliased by s_items[RB*100] after hor)
//  s_misc  wv 20 + bv 4 + bh 80 + b1 128 = 232
#define SM_EMB   0
#define SM_Z     20480
#define SM_WH    (20480 + 24064)
#define SM_MISC  (20480 + 24064 + 10240)
#define SM_FLOATS (20480 + 24064 + 10240 + 232)
#define SM_BYTES  (SM_FLOATS * 4)

__global__ void __launch_bounds__(NTHR, 1)
caser_fused_kernel(const int* __restrict__ d_seq,
                   const int* __restrict__ d_user,
                   const int* __restrict__ d_items,
                   const float* __restrict__ d_item_table,
                   const float* __restrict__ d_user_table,
                   const float* __restrict__ d_Wv,
                   const float* __restrict__ d_bv,
                   const float* __restrict__ d_Wh,
                   const float* __restrict__ d_bh,
                   const float* __restrict__ d_W1,
                   const float* __restrict__ d_b1,
                   const float* __restrict__ d_W2,
                   const float* __restrict__ d_b2,
                   float* __restrict__ d_out)
{
    extern __shared__ float smem[];
    float* s_emb = smem + SM_EMB;   // also s_xc after hor
    float* s_z   = smem + SM_Z;
    float* s_wh  = smem + SM_WH;    // also s_items after hor
    float* s_wv  = smem + SM_MISC;          // 20
    float* s_bv  = s_wv + 20;               // 4
    float* s_bh  = s_bv + 4;                // 80
    float* s_b1  = s_bh + 80;               // 128

    const int tid  = threadIdx.x;
    const int wid  = tid >> 5;
    const int lane = tid & 31;
    const int base = blockIdx.x * RB;

    // ---- Phase 0: small weights + seq indices (seq cached in s_wh temp) ----
    if (tid < 20)        s_wv[tid] = d_Wv[tid];
    else if (tid < 24)   s_bv[tid - 20] = d_bv[tid - 20];
    else if (tid < 104)  s_bh[tid - 24] = d_bh[tid - 24];
    else if (tid < 232)  s_b1[tid - 104] = d_b1[tid - 104];

    int* s_seq = (int*)s_wh;                // 160 ints, temporary
    if (tid < RB * LL) s_seq[tid] = d_seq[base * LL + tid];
    __syncthreads();

    // ---- Phase 1: gather item embeddings: 32 rows x 5 items x 128 f ----
    {
        const float4* it4 = (const float4*)d_item_table;
        float4* e4 = (float4*)s_emb;
        #pragma unroll
        for (int i = tid; i < RB * LL * (DD / 4); i += NTHR) {
            int ri = i >> 5;          // (row,item) pair
            int d4 = i & 31;
            int idx = s_seq[ri];
            e4[i] = it4[(size_t)idx * 32 + d4];
        }
    }
    __syncthreads();

    // ---- Phase 2: vertical conv -> z[ : , 0..512) ----
    for (int o = tid; o < RB * NVV * DD; o += NTHR) {
        int r = o >> 9;
        int j = o & 511;
        int v = j >> 7;
        int d = j & 127;
        const float* e = s_emb + r * 640 + d;
        float acc = s_bv[v];
        #pragma unroll
        for (int t = 0; t < 5; t++) acc = fmaf(e[t * 128], s_wv[v * 5 + t], acc);
        s_z[r * FC1 + j] = acc;
    }

    // ---- Phase 3: horizontal convs -> z[ :, 512..752) ----
    const int zoff_tab[5] = {512, 592, 656, 704, 736};
    #pragma unroll
    for (int l = 1; l <= 5; l++) {
        const int lout = 6 - l;
        const int zoff = zoff_tab[l - 1];
        __syncthreads();   // protect s_wh reuse (seq cache / previous l)
        // stage Wh_l: [16][l][128] floats
        {
            const float4* wsrc = (const float4*)d_Wh;
            float4* wdst = (float4*)s_wh;
            for (int i = tid; i < 16 * l * 32; i += NTHR) {
                int fs = i >> 5, d4 = i & 31;
                int f = fs / l, s = fs - f * l;
                wdst[i] = wsrc[((l - 1) * 16 + f) * 160 + s * 32 + d4];
            }
        }
        __syncthreads();
        const int nout = RB * 16 * lout;
        for (int o = wid; o < nout; o += NWARP) {
            int r = o / (16 * lout);
            int j = o - r * (16 * lout);
            int f = j / lout;
            int t = j - f * lout;
            const float4* e4 = (const float4*)(s_emb + r * 640 + t * 128);
            const float4* w4 = (const float4*)(s_wh + f * (l * 128));
            float acc = 0.f;
            #pragma unroll
            for (int k4 = 0; k4 < l; k4++) {
                float4 ev = e4[k4 * 32 + lane];
                float4 wv = w4[k4 * 32 + lane];
                acc += ev.x * wv.x + ev.y * wv.y + ev.z * wv.z + ev.w * wv.w;
            }
            #pragma unroll
            for (int sft = 16; sft; sft >>= 1)
                acc += __shfl_xor_sync(0xffffffffu, acc, sft);
            if (lane == 0) {
                float h = acc + s_bh[(l - 1) * 16 + f];
                s_z[r * FC1 + zoff + f * lout + t] = fmaxf(h, 0.f);
            }
        }
    }
    __syncthreads();   // z complete; s_emb dead; s_wh dead

    float* s_xc = s_emb;                    // [RB][256]
    int* s_items = (int*)s_wh;              // [RB*100]

    // ---- Phase 4a: gather user embeddings into xc[:,128..256) ----
    {
        const float4* ut4 = (const float4*)d_user_table;
        for (int o = tid; o < RB * 32; o += NTHR) {
            int r = o >> 5, d4 = o & 31;
            int u = d_user[base + r];
            ((float4*)s_xc)[r * 64 + 32 + d4] = ut4[(size_t)u * 32 + d4];
        }
    }
    // ---- Phase 4b: stage item ids ----
    for (int i = tid; i < RB * TT; i += NTHR)
        s_items[i] = d_items[base * TT + i];

    // ---- Phase 5: FC1: x = relu(z @ W1 + b1) -> xc[:,0..128) ----
    {
        const int d  = tid & 127;
        const int rh = tid >> 7;            // 0..3, 8 rows each
        float acc[8];
        #pragma unroll
        for (int i = 0; i < 8; i++) acc[i] = 0.f;
        const float* __restrict__ w1p = d_W1 + d;
        const float* zb0 = s_z + rh * 8 * FC1;
        #pragma unroll 2
        for (int k = 0; k < FC1; k += 4) {
            float wa = __ldg(w1p + (k + 0) * 128);
            float wb = __ldg(w1p + (k + 1) * 128);
            float wc = __ldg(w1p + (k + 2) * 128);
            float wd = __ldg(w1p + (k + 3) * 128);
            #pragma unroll
            for (int i = 0; i < 8; i++) {
                float4 zv = *(const float4*)(zb0 + i * FC1 + k);
                acc[i] = fmaf(zv.x, wa, acc[i]);
                acc[i] = fmaf(zv.y, wb, acc[i]);
                acc[i] = fmaf(zv.z, wc, acc[i]);
                acc[i] = fmaf(zv.w, wd, acc[i]);
            }
        }
        float bb = s_b1[d];
        #pragma unroll
        for (int i = 0; i < 8; i++) {
            int r = rh * 8 + i;
            s_xc[r * 256 + d] = fmaxf(acc[i] + bb, 0.f);
        }
    }
    __syncthreads();

    // ---- Phase 6: scoring: out[b,t] = dot(W2[item], xc[b]) + b2[item] ----
    {
        const int o0 = wid * (RB * TT / NWARP);   // 200 dots per warp
        for (int u = 0; u < RB * TT / NWARP; u += 4) {
            float acc[4];
            #pragma unroll
            for (int q = 0; q < 4; q++) {
                int oo = o0 + u + q;
                int item = s_items[oo];
                int r = oo / 100;
                const float4* w2 = (const float4*)(d_W2 + (size_t)item * 256);
                const float4* xc4 = (const float4*)(s_xc + r * 256);
                float4 a0 = w2[lane];
                float4 a1 = w2[lane + 32];
                float4 c0 = xc4[lane];
                float4 c1 = xc4[lane + 32];
                acc[q] = a0.x * c0.x + a0.y * c0.y + a0.z * c0.z + a0.w * c0.w
                       + a1.x * c1.x + a1.y * c1.y + a1.z * c1.z + a1.w * c1.w;
            }
            #pragma unroll
            for (int q = 0; q < 4; q++) {
                #pragma unroll
                for (int sft = 16; sft; sft >>= 1)
                    acc[q] += __shfl_xor_sync(0xffffffffu, acc[q], sft);
            }
            if (lane == 0) {
                #pragma unroll
                for (int q = 0; q < 4; q++) {
                    int oo = o0 + u + q;
                    d_out[base * TT + oo] = acc[q] + __ldg(d_b2 + s_items[oo]);
                }
            }
        }
    }
}

extern "C" void kernel_launch(void* const* d_in, const int* in_sizes, int n_in,
                              void* d_out, int out_size)
{
    const int*   seq        = (const int*)  d_in[0];
    const int*   user       = (const int*)  d_in[1];
    const int*   items      = (const int*)  d_in[2];
    const float* item_table = (const float*)d_in[3];
    const float* user_table = (const float*)d_in[4];
    const float* Wv         = (const float*)d_in[5];
    const float* bv         = (const float*)d_in[6];
    const float* Wh         = (const float*)d_in[7];
    const float* bh         = (const float*)d_in[8];
    const float* W1         = (const float*)d_in[9];
    const float* b1         = (const float*)d_in[10];
    const float* W2         = (const float*)d_in[11];
    const float* b2         = (const float*)d_in[12];
    (void)in_sizes; (void)n_in;

    cudaFuncSetAttribute(caser_fused_kernel,
                         cudaFuncAttributeMaxDynamicSharedMemorySize, SM_BYTES);

    caser_fused_kernel<<<BB / RB, NTHR, SM_BYTES>>>(
        seq, user, items, item_table, user_table,
        Wv, bv, Wh, bh, W1, b1, W2, b2, (float*)d_out);
}